// round 7
// baseline (speedup 1.0000x reference)
#include <cuda_runtime.h>
#include <cuda_bf16.h>
#include <cstdint>

#define GNX 512
#define GNY 512
#define GP (GNX * GNY)          // 262144 pillars
#define GB 4
#define GNPTS 100000
#define GC 64
#define TILE_P 64               // pillars per tile
#define TILES_PER_B (GP / TILE_P)   // 4096
#define NTILES (GB * TILES_PER_B)   // 16384
#define NPTS_TOTAL (GB * GNPTS)     // 400000

// Small CSR buffers (≈1.8 MB total) — no dense scratch.
// g_hist must be zero at entry of every kernel_launch: zero at module load,
// then scan_kernel re-zeroes it behind its read on every invocation.
__device__ int      g_hist[NTILES];
__device__ int      g_off[NTILES + 1];
__device__ int      g_cursor[NTILES];
__device__ unsigned g_list[NPTS_TOTAL];

// ---------------------------------------------------------------------------
// K1: per-tile histogram. 4 points/thread via int4 (MLP=4, no atomic returns
// -> REDG). Indices are int32 on the wire (JAX x64-off). GNPTS % 4 == 0, so a
// group of 4 never straddles a batch boundary.
// ---------------------------------------------------------------------------
__global__ void hist_kernel(const int* __restrict__ indices) {
    int t = blockIdx.x * blockDim.x + threadIdx.x;
    if (t >= NPTS_TOTAL / 4) return;
    int b = (t * 4) / GNPTS;
    int4 p4 = reinterpret_cast<const int4*>(indices)[t];
    int base = b * TILES_PER_B;
    if (p4.x >= 0 && p4.x < GP) atomicAdd(&g_hist[base + (p4.x >> 6)], 1);
    if (p4.y >= 0 && p4.y < GP) atomicAdd(&g_hist[base + (p4.y >> 6)], 1);
    if (p4.z >= 0 && p4.z < GP) atomicAdd(&g_hist[base + (p4.z >> 6)], 1);
    if (p4.w >= 0 && p4.w < GP) atomicAdd(&g_hist[base + (p4.w >> 6)], 1);
}

// ---------------------------------------------------------------------------
// K2: single-block exclusive scan of 16384 counters (1024 thr x 16 elems).
// Writes g_off + seeds g_cursor, and ZEROES g_hist behind the read so the
// next invocation (graph replay) starts clean without a separate kernel.
// ---------------------------------------------------------------------------
__global__ void scan_kernel() {
    __shared__ int warp_sums[32];
    int tid  = threadIdx.x;
    int lane = tid & 31, wid = tid >> 5;
    int base = tid * 16;

    int vals[16];
    int s = 0;
#pragma unroll
    for (int i = 0; i < 16; i++) {
        vals[i] = g_hist[base + i];
        g_hist[base + i] = 0;          // free re-zero (line already dirty)
        s += vals[i];
    }

    int inc = s;
#pragma unroll
    for (int o = 1; o < 32; o <<= 1) {
        int v = __shfl_up_sync(0xFFFFFFFFu, inc, o);
        if (lane >= o) inc += v;
    }
    if (lane == 31) warp_sums[wid] = inc;
    __syncthreads();
    if (wid == 0) {
        int w = warp_sums[lane];
#pragma unroll
        for (int o = 1; o < 32; o <<= 1) {
            int v = __shfl_up_sync(0xFFFFFFFFu, w, o);
            if (lane >= o) w += v;
        }
        warp_sums[lane] = w;
    }
    __syncthreads();

    int excl = ((wid == 0) ? 0 : warp_sums[wid - 1]) + (inc - s);
    int run = excl;
#pragma unroll
    for (int i = 0; i < 16; i++) {
        g_off[base + i]    = run;
        g_cursor[base + i] = run;
        run += vals[i];
    }
    if (tid == 1023) g_off[NTILES] = run;
}

// ---------------------------------------------------------------------------
// K3: fill point list, 4 points/thread (4 independent ATOMG chains).
// entry = (pillar & 63) << 20 | global_point_id  (400000 < 2^20).
// ---------------------------------------------------------------------------
__global__ void fill_kernel(const int* __restrict__ indices) {
    int t = blockIdx.x * blockDim.x + threadIdx.x;
    if (t >= NPTS_TOTAL / 4) return;
    int b = (t * 4) / GNPTS;
    int4 p4 = reinterpret_cast<const int4*>(indices)[t];
    int base = b * TILES_PER_B;
    int p[4] = {p4.x, p4.y, p4.z, p4.w};
#pragma unroll
    for (int k = 0; k < 4; k++) {
        if (p[k] >= 0 && p[k] < GP) {
            int pos = atomicAdd(&g_cursor[base + (p[k] >> 6)], 1);
            g_list[pos] = ((unsigned)(p[k] & 63) << 20) | (unsigned)(t * 4 + k);
        }
    }
}

// ---------------------------------------------------------------------------
// K4: gather + accumulate + write. One block per 64-pillar tile.
// Half-warp per point: 16 lanes read the 256B feature row as float4 (__ldcs,
// read-once), 4 smem atomicAdds each; 2 points per warp-iteration.
// Then stream the 16 KB (64c x 64p) tile to out with __stwt (bypass L2).
// ---------------------------------------------------------------------------
__global__ void gather_kernel(const float* __restrict__ x,
                              float* __restrict__ out) {
    __shared__ float acc[GC][TILE_P + 1];

    int tid = threadIdx.x;
    for (int i = tid; i < GC * (TILE_P + 1); i += 256)
        ((float*)acc)[i] = 0.0f;
    __syncthreads();

    int tile  = blockIdx.x;
    int start = g_off[tile];
    int end   = g_off[tile + 1];
    int wid   = tid >> 5;
    int lane  = tid & 31;
    int half  = lane >> 4;        // 0 or 1: which point of the pair
    int lh    = lane & 15;        // lane within half-warp

    for (int e0 = start + wid * 2; e0 < end; e0 += 16) {
        int e = e0 + half;
        if (e < end) {
            unsigned ent = g_list[e];
            unsigned gid = ent & 0xFFFFFu;
            unsigned plo = ent >> 20;
            float4 v = __ldcs(reinterpret_cast<const float4*>(x + (size_t)gid * GC) + lh);
            atomicAdd(&acc[4 * lh + 0][plo], v.x);
            atomicAdd(&acc[4 * lh + 1][plo], v.y);
            atomicAdd(&acc[4 * lh + 2][plo], v.z);
            atomicAdd(&acc[4 * lh + 3][plo], v.w);
        }
    }
    __syncthreads();

    int b  = tile >> 12;                 // tile / TILES_PER_B
    int p0 = (tile & (TILES_PER_B - 1)) << 6;
    float* obase = out + ((size_t)b * GC) * GP + p0;

    for (int i = tid; i < GC * (TILE_P / 4); i += 256) {
        int c = i >> 4;
        int q = (i & 15) << 2;
        float4 v = make_float4(acc[c][q], acc[c][q + 1], acc[c][q + 2], acc[c][q + 3]);
        __stwt(reinterpret_cast<float4*>(obase + (size_t)c * GP + q), v);
    }
}

extern "C" void kernel_launch(void* const* d_in, const int* in_sizes, int n_in,
                              void* d_out, int out_size) {
    const float* x   = (const float*)d_in[0];   // (B, N, C) fp32
    const int*   idx = (const int*)d_in[1];     // (B, N) int32
    float*       out = (float*)d_out;           // (B, C, NX, NY) fp32

    (void)in_sizes; (void)n_in; (void)out_size;

    hist_kernel<<<(NPTS_TOTAL / 4 + 255) / 256, 256>>>(idx);
    scan_kernel<<<1, 1024>>>();
    fill_kernel<<<(NPTS_TOTAL / 4 + 255) / 256, 256>>>(idx);
    gather_kernel<<<NTILES, 256>>>(x, out);
}